// round 9
// baseline (speedup 1.0000x reference)
#include <cuda_runtime.h>

#define B_SZ   8192
#define IN_SZ  64
#define OUT_SZ 64
#define NS     8
#define NB     20
#define NI     19

#define ROWS_PER_BLK 8      // rows of x per block
#define R_PER_THREAD 4      // rows per thread
#define ZSPLIT 2            // i-dimension split
#define LN2f  0.69314718055994530942f
#define L2Ef  1.44269504088896340736f

// Precomputed per-(o,i) parameter tables, [i*OUT + o] layout (coalesced over o).
// PA = { b1*scale*ln2, b2*ln2, b3*log2e, b4 }
// PB = { b5..b8 * scale },  scale = softplus(raw_gamma)/OUT
__device__ float4 g_PA[IN_SZ * OUT_SZ];
__device__ float4 g_PB[IN_SZ * OUT_SZ];

__device__ __forceinline__ float ex2f(float x) {
    float y; asm("ex2.approx.ftz.f32 %0, %1;" : "=f"(y) : "f"(x)); return y;
}
__device__ __forceinline__ float lg2f(float x) {
    float y; asm("lg2.approx.ftz.f32 %0, %1;" : "=f"(y) : "f"(x)); return y;
}

__global__ void prep_kernel(const float* __restrict__ raw_gamma,
                            const float* __restrict__ w,
                            const float* __restrict__ breaks,
                            const float* __restrict__ coefs,
                            const float* __restrict__ mu_p,
                            const float* __restrict__ sigma_p)
{
    int tid = blockIdx.x * blockDim.x + threadIdx.x;
    if (tid < IN_SZ * OUT_SZ) {
        int o = tid / IN_SZ;
        int i = tid % IN_SZ;

        float mu = mu_p[0];
        float sigma = sigma_p[0];

        float wv = w[o * IN_SZ + i];
        wv = fminf(fmaxf(wv, -5.5f), 37.9f);
        float wn = (wv - mu) / sigma;

        float b[NS];
#pragma unroll
        for (int s = 0; s < NS; s++) {
            const float* br = breaks + s * NB;
            float lo = br[0];
            float hi = br[NB - 1] - 1e-6f;
            float wl = fminf(fmaxf(wn, lo), hi);
            // searchsorted(br, wl, 'left') - 1  ==  (#elements < wl) - 1
            int idx = -1;
#pragma unroll
            for (int j = 0; j < NB; j++) idx += (br[j] < wl) ? 1 : 0;
            idx = max(0, min(idx, NI - 1));
            const float* cf = coefs + (s * NI + idx) * 4;
            float t = wl - br[idx];
            b[s] = ((cf[0] * t + cf[1]) * t + cf[2]) * t + cf[3];
        }

        float g = raw_gamma[o * IN_SZ + i];
        float sp = fmaxf(g, 0.0f) + log1pf(__expf(-fabsf(g)));   // stable softplus
        float scale = sp * (1.0f / OUT_SZ);

        g_PA[i * OUT_SZ + o] = make_float4(b[0] * scale * LN2f,  // b1'
                                           b[1] * LN2f,          // b2'
                                           b[2] * L2Ef,          // b3'
                                           b[3]);                // b4
        g_PB[i * OUT_SZ + o] = make_float4(b[4] * scale, b[5] * scale,
                                           b[6] * scale, b[7] * scale);
    }
    // Flush point for PDL: writes above are visible to the dependent grid
    // after its griddepcontrol.wait.
    asm volatile("griddepcontrol.launch_dependents;");
}

// One live evaluation: 5 MUFU + 10 fma-pipe ops.
__device__ __forceinline__ void eval1(float x, float4 pa, float4 pb, float& acc)
{
    float e     = ex2f(pa.z * x);            // exp(b3*x) == 2^(b3' x)
    float u     = e - 1.0f;
    float p     = ex2f(pa.w * lg2f(u));      // u^b4
    float L1    = lg2f(1.0f + p);            // log1p/ln2
    float inner = fmaf(pa.y, L1, 1.0f);      // 1 + b2*log1p
    float L2    = lg2f(inner);
    float h     = fmaf(pb.w, x, pb.z);
    h           = fmaf(h, x, pb.y);
    h           = fmaf(h, x, pb.x);
    acc         = fmaf(x, h, acc);
    acc         = fmaf(pa.x, L2, acc);       // + b1*scale*ln(inner)
}

// block = (64, 2, 2): x=o, y=row-group (4 rows each), z=i-half
__global__ __launch_bounds__(OUT_SZ * 2 * ZSPLIT, 7)
void main_kernel(const float* __restrict__ x, float* __restrict__ out)
{
    // transposed x tile: sxT[i][row], stride 12 words (48B) keeps 16B
    // alignment for LDS.128 at row offsets 0 and 4.
    __shared__ float sxT[IN_SZ][12];
    __shared__ float red[2][R_PER_THREAD][OUT_SZ];   // z=1 partials

    const int o  = threadIdx.x;                    // 0..63 (output index)
    const int ry = threadIdx.y;                    // 0..1 (row group)
    const int z  = threadIdx.z;                    // 0..1 (i half)
    const int t  = threadIdx.x + 64 * ry + 128 * z; // 0..255
    const int rowBase = blockIdx.x * ROWS_PER_BLK;

    // fill: 8 rows x 64 cols, coalesced global reads, transposed store.
    // Independent of the prep tables -> runs before griddepcontrol.wait.
#pragma unroll
    for (int k = 0; k < 2; k++) {
        int idx = t + k * 256;                     // 0..511
        int r = idx >> 6;                          // 0..7
        int c = idx & 63;                          // 0..63
        sxT[c][r] = fmaxf(x[(rowBase + r) * IN_SZ + c], 0.0f);
    }
    __syncthreads();

    // Wait for prep's table writes (PDL dependency).
    asm volatile("griddepcontrol.wait;");

    float acc0 = 0.f, acc1 = 0.f, acc2 = 0.f, acc3 = 0.f;
    const int iBase = z * (IN_SZ / ZSPLIT);

#pragma unroll 2
    for (int ii = 0; ii < IN_SZ / ZSPLIT; ii++) {
        const int i = iBase + ii;
        // broadcast LDS.128: all lanes in a warp read the same address
        float4 xv = *reinterpret_cast<const float4*>(&sxT[i][ry * R_PER_THREAD]);
        float4 pa = g_PA[i * OUT_SZ + o];
        float4 pb = g_PB[i * OUT_SZ + o];
        if (xv.x > 0.0f) eval1(xv.x, pa, pb, acc0);   // warp-uniform branches
        if (xv.y > 0.0f) eval1(xv.y, pa, pb, acc1);
        if (xv.z > 0.0f) eval1(xv.z, pa, pb, acc2);
        if (xv.w > 0.0f) eval1(xv.w, pa, pb, acc3);
    }

    // 2-way reduction over the i-split
    if (z == 1) {
        red[ry][0][o] = acc0;
        red[ry][1][o] = acc1;
        red[ry][2][o] = acc2;
        red[ry][3][o] = acc3;
    }
    __syncthreads();
    if (z == 0) {
        const int row = rowBase + ry * R_PER_THREAD;
        out[(row + 0) * OUT_SZ + o] = acc0 + red[ry][0][o];
        out[(row + 1) * OUT_SZ + o] = acc1 + red[ry][1][o];
        out[(row + 2) * OUT_SZ + o] = acc2 + red[ry][2][o];
        out[(row + 3) * OUT_SZ + o] = acc3 + red[ry][3][o];
    }
}

extern "C" void kernel_launch(void* const* d_in, const int* in_sizes, int n_in,
                              void* d_out, int out_size)
{
    // metadata order: x, raw_gamma, w, breaks, coefs, mu_detuning, sigma_detuning
    const float* x         = (const float*)d_in[0];
    const float* raw_gamma = (const float*)d_in[1];
    const float* w         = (const float*)d_in[2];
    const float* breaks    = (const float*)d_in[3];
    const float* coefs     = (const float*)d_in[4];
    const float* mu        = (const float*)d_in[5];
    const float* sigma     = (const float*)d_in[6];
    float* out = (float*)d_out;

    prep_kernel<<<32, 128>>>(raw_gamma, w, breaks, coefs, mu, sigma);

    // Main kernel launched with programmatic dependent launch: its launch ramp
    // and x/smem fill overlap prep's execution; the table dependency is
    // enforced by griddepcontrol.wait inside the kernel.
    cudaLaunchConfig_t cfg = {};
    cfg.gridDim  = dim3(B_SZ / ROWS_PER_BLK);
    cfg.blockDim = dim3(OUT_SZ, 2, ZSPLIT);
    cfg.dynamicSmemBytes = 0;
    cudaLaunchAttribute attrs[1];
    attrs[0].id = cudaLaunchAttributeProgrammaticStreamSerialization;
    attrs[0].val.programmaticStreamSerializationAllowed = 1;
    cfg.attrs = attrs;
    cfg.numAttrs = 1;
    cudaLaunchKernelEx(&cfg, main_kernel, x, out);
}

// round 10
// speedup vs baseline: 1.0696x; 1.0696x over previous
#include <cuda_runtime.h>

#define B_SZ   8192
#define IN_SZ  64
#define OUT_SZ 64
#define NS     8
#define NB     20
#define NI     19

#define ROWS_PER_BLK 4
#define LN2f  0.69314718055994530942f
#define L2Ef  1.44269504088896340736f

// Precomputed per-(o,i) parameter tables, [i*OUT + o] layout (coalesced over o).
// PA = { b1*scale*ln2, b2*ln2, b3*log2e, b4 }
// PB = { b5..b8 * scale },  scale = softplus(raw_gamma)/OUT
__device__ float4 g_PA[IN_SZ * OUT_SZ];
__device__ float4 g_PB[IN_SZ * OUT_SZ];

__device__ __forceinline__ float ex2f(float x) {
    float y; asm("ex2.approx.ftz.f32 %0, %1;" : "=f"(y) : "f"(x)); return y;
}
__device__ __forceinline__ float lg2f(float x) {
    float y; asm("lg2.approx.ftz.f32 %0, %1;" : "=f"(y) : "f"(x)); return y;
}

__global__ void prep_kernel(const float* __restrict__ raw_gamma,
                            const float* __restrict__ w,
                            const float* __restrict__ breaks,
                            const float* __restrict__ coefs,
                            const float* __restrict__ mu_p,
                            const float* __restrict__ sigma_p)
{
    int tid = blockIdx.x * blockDim.x + threadIdx.x;
    if (tid < IN_SZ * OUT_SZ) {
        int o = tid / IN_SZ;
        int i = tid % IN_SZ;

        float mu = mu_p[0];
        float sigma = sigma_p[0];

        float wv = w[o * IN_SZ + i];
        wv = fminf(fmaxf(wv, -5.5f), 37.9f);
        float wn = (wv - mu) / sigma;

        float b[NS];
#pragma unroll
        for (int s = 0; s < NS; s++) {
            const float* br = breaks + s * NB;
            float lo = br[0];
            float hi = br[NB - 1] - 1e-6f;
            float wl = fminf(fmaxf(wn, lo), hi);
            // searchsorted(br, wl, 'left') - 1  ==  (#elements < wl) - 1
            int idx = -1;
#pragma unroll
            for (int j = 0; j < NB; j++) idx += (br[j] < wl) ? 1 : 0;
            idx = max(0, min(idx, NI - 1));
            const float* cf = coefs + (s * NI + idx) * 4;
            float t = wl - br[idx];
            b[s] = ((cf[0] * t + cf[1]) * t + cf[2]) * t + cf[3];
        }

        float g = raw_gamma[o * IN_SZ + i];
        float sp = fmaxf(g, 0.0f) + log1pf(__expf(-fabsf(g)));   // stable softplus
        float scale = sp * (1.0f / OUT_SZ);

        g_PA[i * OUT_SZ + o] = make_float4(b[0] * scale * LN2f,  // b1'
                                           b[1] * LN2f,          // b2'
                                           b[2] * L2Ef,          // b3'
                                           b[3]);                // b4
        g_PB[i * OUT_SZ + o] = make_float4(b[4] * scale, b[5] * scale,
                                           b[6] * scale, b[7] * scale);
    }
    // PDL flush: table writes are visible to the dependent grid after its wait.
    asm volatile("griddepcontrol.launch_dependents;");
}

// block = (64, 4): one warp = one row x 32 o's (2 warps per row).
// Phase 1: load x, ballot-compact live i's per row into smem.
// Phase 2: branchless loop over the compacted list only.
__global__ __launch_bounds__(OUT_SZ * ROWS_PER_BLK, 8)
void main_kernel(const float* __restrict__ x, float* __restrict__ out)
{
    __shared__ float  rawx[ROWS_PER_BLK][IN_SZ];
    __shared__ float2 comp[ROWS_PER_BLK][IN_SZ];   // (x, float-bits of i*64)
    __shared__ int    cnt[ROWS_PER_BLK];

    const int o    = threadIdx.x;              // 0..63 (output index)
    const int ry   = threadIdx.y;              // 0..3  (row within block)
    const int row  = blockIdx.x * ROWS_PER_BLK + ry;
    const int lane = o & 31;

    // coalesced x load (256 consecutive floats across the block)
    rawx[ry][o] = fmaxf(x[row * IN_SZ + o], 0.0f);
    __syncthreads();

    // lower warp of each row compacts the 64 entries (order-preserving)
    if (o < 32) {
        float v0 = rawx[ry][lane];
        float v1 = rawx[ry][lane + 32];
        unsigned m0 = __ballot_sync(0xffffffffu, v0 > 0.0f);
        unsigned m1 = __ballot_sync(0xffffffffu, v1 > 0.0f);
        int n0 = __popc(m0);
        unsigned below = (1u << lane) - 1u;
        if (v0 > 0.0f) {
            int p = __popc(m0 & below);
            comp[ry][p] = make_float2(v0, __int_as_float(lane << 6));
        }
        if (v1 > 0.0f) {
            int p = n0 + __popc(m1 & below);
            comp[ry][p] = make_float2(v1, __int_as_float((lane + 32) << 6));
        }
        if (lane == 0) cnt[ry] = n0 + __popc(m1);
    }
    __syncthreads();

    // Wait for prep's table writes (PDL dependency).
    asm volatile("griddepcontrol.wait;");

    const int n = cnt[ry];
    float acc = 0.0f;

#pragma unroll 2
    for (int c = 0; c < n; c++) {
        float2 e = comp[ry][c];                 // broadcast LDS.64
        float xv = e.x;
        int ib   = __float_as_int(e.y);         // i*64
        float4 pa = g_PA[ib + o];
        float4 pb = g_PB[ib + o];

        float ex    = ex2f(pa.z * xv);          // exp(b3*x) == 2^(b3' x)
        float u     = ex - 1.0f;
        float p     = ex2f(pa.w * lg2f(u));     // u^b4
        float L1    = lg2f(1.0f + p);           // log1p/ln2
        float inner = fmaf(pa.y, L1, 1.0f);     // 1 + b2*log1p
        float L2    = lg2f(inner);
        float h     = fmaf(pb.w, xv, pb.z);
        h           = fmaf(h, xv, pb.y);
        h           = fmaf(h, xv, pb.x);
        acc         = fmaf(xv, h, acc);
        acc         = fmaf(pa.x, L2, acc);      // + b1*scale*ln(inner)
    }

    out[row * OUT_SZ + o] = acc;
}

extern "C" void kernel_launch(void* const* d_in, const int* in_sizes, int n_in,
                              void* d_out, int out_size)
{
    // metadata order: x, raw_gamma, w, breaks, coefs, mu_detuning, sigma_detuning
    const float* x         = (const float*)d_in[0];
    const float* raw_gamma = (const float*)d_in[1];
    const float* w         = (const float*)d_in[2];
    const float* breaks    = (const float*)d_in[3];
    const float* coefs     = (const float*)d_in[4];
    const float* mu        = (const float*)d_in[5];
    const float* sigma     = (const float*)d_in[6];
    float* out = (float*)d_out;

    prep_kernel<<<32, 128>>>(raw_gamma, w, breaks, coefs, mu, sigma);

    // PDL: main's launch ramp + x-load + compaction overlap prep's execution.
    cudaLaunchConfig_t cfg = {};
    cfg.gridDim  = dim3(B_SZ / ROWS_PER_BLK);
    cfg.blockDim = dim3(OUT_SZ, ROWS_PER_BLK);
    cfg.dynamicSmemBytes = 0;
    cudaLaunchAttribute attrs[1];
    attrs[0].id = cudaLaunchAttributeProgrammaticStreamSerialization;
    attrs[0].val.programmaticStreamSerializationAllowed = 1;
    cfg.attrs = attrs;
    cfg.numAttrs = 1;
    cudaLaunchKernelEx(&cfg, main_kernel, x, out);
}